// round 13
// baseline (speedup 1.0000x reference)
#include <cuda_runtime.h>

// SofaNetEllipse via Chebyshev spectral compression (NQ=16) — two kernels.
//
// Kernel A: exact MLP+JVP at 16 Chebyshev nodes per network, 2 threads/node,
//           TPBA=32. Layer-1 uses packed fma.rn.f32x2 with 2 rows per
//           iteration (4 chains of 32 deps) — halves the dependent-chain
//           critical path, which binds at 1 warp/block occupancy.
// Kernel B: Clenshaw (15 iters, packed f32x2), 4 clean tiles; xlast computed
//           analytically per-thread (T_k(1)=1 => p0(1)=sum(c_k)), removing
//           the tile-0 sync and the column remap.

#define NAB   1024
#define NCOL  2049
#define HALF  1025
#define H     64
#define TPBA  32      // kernel A: one warp, 2 threads/node x 16 nodes
#define TPB2  256     // kernel B
#define NQ    16      // Chebyshev nodes / coefficients

#define XH    0.7853981633974483f   // pi/4  (half-width of [0, pi/2])
#define INVXH 1.2732395447351628f   // 4/pi  (s = alpha*INVXH - 1)

typedef unsigned long long u64;

__device__ __align__(16) float4 g_coef[NAB * NQ];   // 256 KB scratch

__device__ __forceinline__ float fast_tanh(float x) {
    // tanh(x) = 1 - 2/(exp(2x)+1); abs err ~1e-6, saturates correctly.
    float e = __expf(x + x);
    return 1.0f - __fdividef(2.0f, e + 1.0f);
}

__device__ __forceinline__ u64 fma2(u64 a, u64 b, u64 c) {
    u64 d;
    asm("fma.rn.f32x2 %0, %1, %2, %3;" : "=l"(d) : "l"(a), "l"(b), "l"(c));
    return d;
}
__device__ __forceinline__ u64 pack2(float lo, float hi) {
    u64 r;
    asm("mov.b64 %0, {%1, %2};" : "=l"(r) : "f"(lo), "f"(hi));
    return r;
}
__device__ __forceinline__ float2 unpack2(u64 v) {
    float2 r;
    asm("mov.b64 {%0, %1}, %2;" : "=f"(r.x), "=f"(r.y) : "l"(v));
    return r;
}

// ======================= Kernel A: coefficients =======================
__global__ __launch_bounds__(TPBA)
void sofanet_coef_kernel(const float* __restrict__ w0,
                         const float* __restrict__ w1,
                         const float* __restrict__ w2,
                         const float* __restrict__ b0,
                         const float* __restrict__ b1,
                         const float* __restrict__ b2)
{
    const int n   = blockIdx.x;   // network id
    const int tid = threadIdx.x;  // 0..31

    __shared__ __align__(16) float  w1s[H * H];   // 16 KB
    __shared__ float w0s[H], b0s[H], b1s[H];
    __shared__ float w2s[2 * H];
    __shared__ float b2s[2];
    __shared__ __align__(16) float4 nodes[NQ];    // f(x_q) = (p0,p1,q0,q1)

    // ---- stage weights (32 threads) ----
    {
        const float4* src = reinterpret_cast<const float4*>(w1 + (size_t)n * H * H);
        float4* dst = reinterpret_cast<float4*>(w1s);
        #pragma unroll
        for (int i = tid; i < (H * H) / 4; i += TPBA) dst[i] = src[i];

        w0s[tid]      = w0[(size_t)n * H + tid];
        w0s[tid + 32] = w0[(size_t)n * H + tid + 32];
        b0s[tid]      = b0[(size_t)n * H + tid];
        b0s[tid + 32] = b0[(size_t)n * H + tid + 32];
        b1s[tid]      = b1[(size_t)n * H + tid];
        b1s[tid + 32] = b1[(size_t)n * H + tid + 32];
        #pragma unroll
        for (int r = 0; r < 4; ++r)
            w2s[tid + 32 * r] = w2[(size_t)n * 2 * H + tid + 32 * r];
        if (tid < 2) b2s[tid] = b2[(size_t)n * 2 + tid];
    }
    __syncthreads();

    // ---- exact MLP + JVP at 16 Chebyshev nodes (2 threads per node) ----
    {
        const int q    = tid >> 1;        // node 0..15
        const int half = tid & 1;         // row half
        const float theta = (2 * q + 1) * (3.14159265358979323846f / (2.0f * NQ));
        const float xq = XH * (1.0f + cosf(theta));   // node in [0, pi/2]

        // layer 0 packed: h2[jj] = (h1[2jj], h1[2jj+1]); same for d2.
        u64 h2[H / 2], d2[H / 2];
        #pragma unroll
        for (int jj = 0; jj < H / 2; ++jj) {
            const float wA  = w0s[2 * jj],     wB  = w0s[2 * jj + 1];
            const float thA = fast_tanh(fmaf(wA, xq, b0s[2 * jj]));
            const float thB = fast_tanh(fmaf(wB, xq, b0s[2 * jj + 1]));
            h2[jj] = pack2(thA, thB);
            d2[jj] = pack2((1.0f - thA * thA) * wA, (1.0f - thB * thB) * wB);
        }

        // layer 1: 2 rows per iteration, packed chains (R3-verified pattern)
        float p0 = 0.f, p1 = 0.f, q0 = 0.f, q1 = 0.f;
        const int i0 = half * 32;
        #pragma unroll 2
        for (int i = i0; i < i0 + 32; i += 2) {
            u64 u0 = 0ull, v0 = 0ull, u1 = 0ull, v1 = 0ull;
            const ulonglong2* ra = reinterpret_cast<const ulonglong2*>(&w1s[i * H]);
            const ulonglong2* rb = reinterpret_cast<const ulonglong2*>(&w1s[i * H + H]);
            #pragma unroll
            for (int j = 0; j < 16; ++j) {       // 16 x LDS.128 per row
                const ulonglong2 wa = ra[j];     // (w[4j],w[4j+1]),(w[4j+2],w[4j+3])
                const ulonglong2 wb = rb[j];
                u0 = fma2(wa.x, h2[2 * j], u0);
                u0 = fma2(wa.y, h2[2 * j + 1], u0);
                v0 = fma2(wa.x, d2[2 * j], v0);
                v0 = fma2(wa.y, d2[2 * j + 1], v0);
                u1 = fma2(wb.x, h2[2 * j], u1);
                u1 = fma2(wb.y, h2[2 * j + 1], u1);
                v1 = fma2(wb.x, d2[2 * j], v1);
                v1 = fma2(wb.y, d2[2 * j + 1], v1);
            }
            const float2 fu0 = unpack2(u0), fv0 = unpack2(v0);
            const float2 fu1 = unpack2(u1), fv1 = unpack2(v1);
            const float sA = (fu0.x + fu0.y) + b1s[i];
            const float sB = (fu1.x + fu1.y) + b1s[i + 1];
            const float tA = fv0.x + fv0.y;
            const float tB = fv1.x + fv1.y;

            const float ha  = fast_tanh(sA);
            const float hb  = fast_tanh(sB);
            const float dda = (1.0f - ha * ha) * tA;
            const float ddb = (1.0f - hb * hb) * tB;
            p0 = fmaf(w2s[i        ], ha,  p0);
            p1 = fmaf(w2s[H + i    ], ha,  p1);
            q0 = fmaf(w2s[i        ], dda, q0);
            q1 = fmaf(w2s[H + i    ], dda, q1);
            p0 = fmaf(w2s[i + 1    ], hb,  p0);
            p1 = fmaf(w2s[H + i + 1], hb,  p1);
            q0 = fmaf(w2s[i + 1    ], ddb, q0);
            q1 = fmaf(w2s[H + i + 1], ddb, q1);
        }

        // combine the two halves (adjacent lanes, same warp, all lanes active)
        p0 += __shfl_xor_sync(0xFFFFFFFFu, p0, 1);
        p1 += __shfl_xor_sync(0xFFFFFFFFu, p1, 1);
        q0 += __shfl_xor_sync(0xFFFFFFFFu, q0, 1);
        q1 += __shfl_xor_sync(0xFFFFFFFFu, q1, 1);

        if (half == 0)
            nodes[q] = make_float4(p0 + b2s[0], p1 + b2s[1], q0, q1);
    }
    __syncthreads();

    // ---- DCT -> Chebyshev coefficients (threads 0..15) -> global ----
    if (tid < NQ) {
        const int k = tid;
        float s0 = 0.f, s1 = 0.f, s2 = 0.f, s3 = 0.f;
        #pragma unroll
        for (int q = 0; q < NQ; ++q) {
            const int m = (k * (2 * q + 1)) & (4 * NQ - 1);   // angle mod 2*pi
            const float c = __cosf((float)m * (3.14159265358979323846f / (2.0f * NQ)));
            const float4 f = nodes[q];
            s0 = fmaf(c, f.x, s0);
            s1 = fmaf(c, f.y, s1);
            s2 = fmaf(c, f.z, s2);
            s3 = fmaf(c, f.w, s3);
        }
        const float sc = (k == 0) ? (1.0f / NQ) : (2.0f / NQ);
        g_coef[n * NQ + k] = make_float4(s0 * sc, s1 * sc, s2 * sc, s3 * sc);
    }
}

// ======================= Kernel B: evaluation =========================
__global__ __launch_bounds__(TPB2, 6)
void sofanet_eval_kernel(const float* __restrict__ alpha,
                         float* __restrict__ out)
{
    const int n   = blockIdx.x;   // network id
    const int tid = threadIdx.x;

    __shared__ __align__(16) float4 coef[NQ];   // 256 B

    // stage coefficients (64 floats, coalesced)
    if (tid < NQ * 4) {
        const float* src = (const float*)(g_coef + (size_t)n * NQ);
        ((float*)coef)[tid] = src[tid];
    }
    __syncthreads();

    const size_t AR  = (size_t)NAB * NCOL;
    const size_t row = (size_t)n * NCOL;

    // xlast = xp at alpha=pi/2 (t=1024): s=1, T_k(1)=1 => p0 = sum_k c_k.x,
    // cos-1 = -1  =>  xlast = -(sum c_k.x)^2. Per-thread, broadcast LDS reads.
    float xlast;
    {
        float S = 0.f;
        #pragma unroll
        for (int k = 0; k < NQ; ++k) S += coef[k].x;
        xlast = -(S * S);
    }

    const u64 NEG1 = pack2(-1.0f, -1.0f);

    // 4 clean tiles: t = k*256 + tid covers 0..1023. Tail t=1024 by tid 0.
    #pragma unroll
    for (int k = 0; k < 4; ++k) {
        const int t = k * TPB2 + tid;

        const float x = alpha[t];
        const float s = fmaf(x, INVXH, -1.0f);
        const float twos = s + s;
        const u64 TWOS = pack2(twos, twos);

        // Clenshaw (packed): b_k = c_k - b_{k+2} + 2s*b_{k+1}
        u64 bAx = 0ull, bAz = 0ull;   // b_{k+1}: (x,y) and (z,w) lanes
        u64 bBx = 0ull, bBz = 0ull;   // b_{k+2}
        const ulonglong2* cp = reinterpret_cast<const ulonglong2*>(coef);
        #pragma unroll
        for (int kk = NQ - 1; kk >= 1; --kk) {
            const ulonglong2 c = cp[kk];
            const u64 nx = fma2(TWOS, bAx, fma2(bBx, NEG1, c.x));
            const u64 nz = fma2(TWOS, bAz, fma2(bBz, NEG1, c.y));
            bBx = bAx;  bBz = bAz;
            bAx = nx;   bAz = nz;
        }
        const float4 c0 = coef[0];
        const float2 aX = unpack2(bAx), aZ = unpack2(bAz);
        const float2 bX = unpack2(bBx), bZ = unpack2(bBz);
        const float p0 = fmaf(s, aX.x, c0.x - bX.x);
        const float p1 = fmaf(s, aX.y, c0.y - bX.y);
        const float q0 = fmaf(s, aZ.x, c0.z - bZ.x);
        const float q1 = fmaf(s, aZ.y, c0.w - bZ.y);

        // square + JVP of square
        const float a  = p0 * p0;
        const float b  = p1 * p1;
        const float da = 2.0f * p0 * q0;
        const float db = 2.0f * p1 * q1;

        // trig epilogue (cos(x)-1 = -2*sin^2(x/2), cancellation-free)
        const float s2v = __sinf(0.5f * x);
        const float cm1 = -2.0f * s2v * s2v;
        const float sa  = __sinf(x);
        const float ca  = 1.0f + cm1;

        const float xp  = a * cm1;
        const float yp  = b * sa;
        const float xpp = fmaf(da, cm1, -a * sa);
        const float ypp = fmaf(db, sa,  b * ca);

        // primary writes (columns 0..1023)
        out[           row + t] = xp;
        out[AR       + row + t] = yp;
        out[2 * AR   + row + t] = xpp;
        out[3 * AR   + row + t] = ypp;

        // mirror writes: dest col 2048 - t
        const int c2 = (NCOL - 1) - t;
        out[           row + c2] = 2.0f * xlast - xp;
        out[AR       + row + c2] = yp;
        out[2 * AR   + row + c2] = xpp;
        out[3 * AR   + row + c2] = -ypp;
    }

    // tail column t=1024 (primary only; it has no mirror image)
    if (tid == 0) {
        const int t = HALF - 1;
        const float x = alpha[t];
        const float s = fmaf(x, INVXH, -1.0f);
        const float twos = s + s;
        const u64 TWOS = pack2(twos, twos);
        u64 bAx = 0ull, bAz = 0ull, bBx = 0ull, bBz = 0ull;
        const ulonglong2* cp = reinterpret_cast<const ulonglong2*>(coef);
        #pragma unroll
        for (int kk = NQ - 1; kk >= 1; --kk) {
            const ulonglong2 c = cp[kk];
            const u64 nx = fma2(TWOS, bAx, fma2(bBx, NEG1, c.x));
            const u64 nz = fma2(TWOS, bAz, fma2(bBz, NEG1, c.y));
            bBx = bAx;  bBz = bAz;
            bAx = nx;   bAz = nz;
        }
        const float4 c0 = coef[0];
        const float2 aX = unpack2(bAx), aZ = unpack2(bAz);
        const float2 bX = unpack2(bBx), bZ = unpack2(bBz);
        const float p0 = fmaf(s, aX.x, c0.x - bX.x);
        const float p1 = fmaf(s, aX.y, c0.y - bX.y);
        const float q0 = fmaf(s, aZ.x, c0.z - bZ.x);
        const float q1 = fmaf(s, aZ.y, c0.w - bZ.y);
        const float a  = p0 * p0;
        const float b  = p1 * p1;
        const float da = 2.0f * p0 * q0;
        const float db = 2.0f * p1 * q1;
        const float s2v = __sinf(0.5f * x);
        const float cm1 = -2.0f * s2v * s2v;
        const float sa  = __sinf(x);
        const float ca  = 1.0f + cm1;
        out[           row + t] = a * cm1;
        out[AR       + row + t] = b * sa;
        out[2 * AR   + row + t] = fmaf(da, cm1, -a * sa);
        out[3 * AR   + row + t] = fmaf(db, sa,  b * ca);
    }
}

extern "C" void kernel_launch(void* const* d_in, const int* in_sizes, int n_in,
                              void* d_out, int out_size)
{
    const float* alpha = (const float*)d_in[0];
    const float* w0    = (const float*)d_in[1];
    const float* w1    = (const float*)d_in[2];
    const float* w2    = (const float*)d_in[3];
    const float* b0    = (const float*)d_in[4];
    const float* b1    = (const float*)d_in[5];
    const float* b2    = (const float*)d_in[6];
    float* out = (float*)d_out;

    sofanet_coef_kernel<<<NAB, TPBA>>>(w0, w1, w2, b0, b1, b2);
    sofanet_eval_kernel<<<NAB, TPB2>>>(alpha, out);
}

// round 15
// speedup vs baseline: 1.0516x; 1.0516x over previous
#include <cuda_runtime.h>

// SofaNetEllipse via Chebyshev spectral compression (NQ=16) — two kernels.
//
// Kernel A: grid 2048 = (network, row-half). Each 32-thread block computes the
//           exact MLP+JVP contribution of 32 of the 64 hidden rows at 16
//           Chebyshev nodes (2 threads/node, 16 rows/thread — R12's verified
//           inner loop), then DCTs its PARTIAL node values (DCT is linear)
//           into g_part[(n,half)]. Doubles warps/SM and halves the per-thread
//           dependency chain vs R12's A.
// Kernel B: R12's proven eval kernel; staging sums the two partial coeffs.

#define NAB   1024
#define NCOL  2049
#define HALF  1025
#define H     64
#define TPBA  32      // kernel A: one warp
#define TPB2  256     // kernel B
#define NQ    16      // Chebyshev nodes / coefficients

#define XH    0.7853981633974483f   // pi/4  (half-width of [0, pi/2])
#define INVXH 1.2732395447351628f   // 4/pi  (s = alpha*INVXH - 1)

typedef unsigned long long u64;

// partial coefficients: [network][half][NQ] float4
__device__ __align__(16) float4 g_part[NAB * 2 * NQ];   // 512 KB scratch

__device__ __forceinline__ float fast_tanh(float x) {
    // tanh(x) = 1 - 2/(exp(2x)+1); abs err ~1e-6, saturates correctly.
    float e = __expf(x + x);
    return 1.0f - __fdividef(2.0f, e + 1.0f);
}

__device__ __forceinline__ u64 fma2(u64 a, u64 b, u64 c) {
    u64 d;
    asm("fma.rn.f32x2 %0, %1, %2, %3;" : "=l"(d) : "l"(a), "l"(b), "l"(c));
    return d;
}
__device__ __forceinline__ u64 pack2(float lo, float hi) {
    u64 r;
    asm("mov.b64 %0, {%1, %2};" : "=l"(r) : "f"(lo), "f"(hi));
    return r;
}
__device__ __forceinline__ float2 unpack2(u64 v) {
    float2 r;
    asm("mov.b64 {%0, %1}, %2;" : "=f"(r.x), "=f"(r.y) : "l"(v));
    return r;
}

// ======================= Kernel A: partial coefficients =======================
__global__ __launch_bounds__(TPBA)
void sofanet_coef_kernel(const float* __restrict__ w0,
                         const float* __restrict__ w1,
                         const float* __restrict__ w2,
                         const float* __restrict__ b0,
                         const float* __restrict__ b1,
                         const float* __restrict__ b2)
{
    const int blk  = blockIdx.x;
    const int n    = blk >> 1;          // network id
    const int rh   = blk & 1;           // row half: rows [rh*32, rh*32+32)
    const int i0   = rh * 32;
    const int tid  = threadIdx.x;       // 0..31

    __shared__ __align__(16) float  w1s[32 * H];  // 8 KB (this half's rows)
    __shared__ float w0s[H], b0s[H], b1h[32];
    __shared__ float w2s[2 * H];
    __shared__ float b2s[2];
    __shared__ __align__(16) float4 nodes[NQ];    // partial f(x_q)

    // ---- stage weights (32 threads) ----
    {
        const float4* src = reinterpret_cast<const float4*>(w1 + (size_t)n * H * H + (size_t)i0 * H);
        float4* dst = reinterpret_cast<float4*>(w1s);
        #pragma unroll
        for (int i = tid; i < (32 * H) / 4; i += TPBA) dst[i] = src[i];

        w0s[tid]      = w0[(size_t)n * H + tid];
        w0s[tid + 32] = w0[(size_t)n * H + tid + 32];
        b0s[tid]      = b0[(size_t)n * H + tid];
        b0s[tid + 32] = b0[(size_t)n * H + tid + 32];
        b1h[tid]      = b1[(size_t)n * H + i0 + tid];
        #pragma unroll
        for (int r = 0; r < 4; ++r)
            w2s[tid + 32 * r] = w2[(size_t)n * 2 * H + tid + 32 * r];
        if (tid < 2) b2s[tid] = b2[(size_t)n * 2 + tid];
    }
    __syncthreads();

    // ---- partial MLP + JVP at 16 Chebyshev nodes (2 threads per node) ----
    {
        const int q   = tid >> 1;        // node 0..15
        const int sub = tid & 1;         // 16-row quarter within this half
        const float theta = (2 * q + 1) * (3.14159265358979323846f / (2.0f * NQ));
        const float xq = XH * (1.0f + cosf(theta));   // node in [0, pi/2]

        // layer 0 (full; small compared to layer 1)
        float h1[H], d1[H];
        #pragma unroll
        for (int j = 0; j < H; ++j) {
            const float w  = w0s[j];
            const float th = fast_tanh(fmaf(w, xq, b0s[j]));
            h1[j] = th;
            d1[j] = (1.0f - th * th) * w;
        }

        // this thread's 16 rows: local rows [sub*16, sub*16+16)
        float p0 = 0.f, p1 = 0.f, q0 = 0.f, q1 = 0.f;
        const int l0 = sub * 16;
        #pragma unroll 2
        for (int l = l0; l < l0 + 16; ++l) {
            float u = b1h[l], v = 0.f;
            const float* ra = &w1s[l * H];
            #pragma unroll
            for (int j = 0; j < H; j += 4) {
                const float4 wa = *reinterpret_cast<const float4*>(ra + j);
                u = fmaf(wa.x, h1[j    ], u);
                u = fmaf(wa.y, h1[j + 1], u);
                u = fmaf(wa.z, h1[j + 2], u);
                u = fmaf(wa.w, h1[j + 3], u);
                v = fmaf(wa.x, d1[j    ], v);
                v = fmaf(wa.y, d1[j + 1], v);
                v = fmaf(wa.z, d1[j + 2], v);
                v = fmaf(wa.w, d1[j + 3], v);
            }
            const float th = fast_tanh(u);
            const float dd = (1.0f - th * th) * v;
            const int i = i0 + l;          // global row index for w2
            p0 = fmaf(w2s[i    ], th, p0);
            p1 = fmaf(w2s[H + i], th, p1);
            q0 = fmaf(w2s[i    ], dd, q0);
            q1 = fmaf(w2s[H + i], dd, q1);
        }

        // combine the two 16-row quarters (adjacent lanes, full warp active)
        p0 += __shfl_xor_sync(0xFFFFFFFFu, p0, 1);
        p1 += __shfl_xor_sync(0xFFFFFFFFu, p1, 1);
        q0 += __shfl_xor_sync(0xFFFFFFFFu, q0, 1);
        q1 += __shfl_xor_sync(0xFFFFFFFFu, q1, 1);

        if (sub == 0) {
            // b2 contributes once per network: fold into half 0 only.
            const float a0 = (rh == 0) ? b2s[0] : 0.0f;
            const float a1 = (rh == 0) ? b2s[1] : 0.0f;
            nodes[q] = make_float4(p0 + a0, p1 + a1, q0, q1);
        }
    }
    __syncthreads();

    // ---- DCT of partial node values (linear) -> g_part[(n,rh)] ----
    if (tid < NQ) {
        const int k = tid;
        float s0 = 0.f, s1 = 0.f, s2 = 0.f, s3 = 0.f;
        #pragma unroll
        for (int q = 0; q < NQ; ++q) {
            const int m = (k * (2 * q + 1)) & (4 * NQ - 1);   // angle mod 2*pi
            const float c = __cosf((float)m * (3.14159265358979323846f / (2.0f * NQ)));
            const float4 f = nodes[q];
            s0 = fmaf(c, f.x, s0);
            s1 = fmaf(c, f.y, s1);
            s2 = fmaf(c, f.z, s2);
            s3 = fmaf(c, f.w, s3);
        }
        const float sc = (k == 0) ? (1.0f / NQ) : (2.0f / NQ);
        g_part[(size_t)blk * NQ + k] = make_float4(s0 * sc, s1 * sc, s2 * sc, s3 * sc);
    }
}

// ======================= Kernel B: evaluation =========================
__global__ __launch_bounds__(TPB2, 6)
void sofanet_eval_kernel(const float* __restrict__ alpha,
                         float* __restrict__ out)
{
    const int n   = blockIdx.x;   // network id
    const int tid = threadIdx.x;

    __shared__ __align__(16) float4 coef[NQ];   // 256 B
    __shared__ float xlast_s;

    // stage coefficients = sum of the two row-half partials (64 floats each)
    if (tid < NQ * 4) {
        const float* s0 = (const float*)(g_part + (size_t)(2 * n) * NQ);
        const float* s1 = (const float*)(g_part + (size_t)(2 * n + 1) * NQ);
        ((float*)coef)[tid] = s0[tid] + s1[tid];
    }
    __syncthreads();

    const size_t AR  = (size_t)NAB * NCOL;
    const size_t row = (size_t)n * NCOL;
    float xlast = 0.0f;
    (void)xlast;

    const u64 NEG1 = pack2(-1.0f, -1.0f);

    // 5 strided tiles cover m = 0..1024 (TPB2=256); remap so m=0 -> t=1024.
    for (int k = 0; k < 5; ++k) {
        const int m = k * TPB2 + tid;
        const bool active = (m < HALF);
        int t = 0;
        if (active) { t = m + (HALF - 1); if (t >= HALF) t -= HALF; }  // bijection

        float xp = 0.f, yp = 0.f, xpp = 0.f, ypp = 0.f;

        if (active) {
            const float x = alpha[t];
            const float s = fmaf(x, INVXH, -1.0f);
            const float twos = s + s;
            const u64 TWOS = pack2(twos, twos);

            // Clenshaw (packed): b_k = c_k - b_{k+2} + 2s*b_{k+1}
            u64 bAx = 0ull, bAz = 0ull;   // b_{k+1}: (x,y) and (z,w) lanes
            u64 bBx = 0ull, bBz = 0ull;   // b_{k+2}
            const ulonglong2* cp = reinterpret_cast<const ulonglong2*>(coef);
            #pragma unroll
            for (int kk = NQ - 1; kk >= 1; --kk) {
                const ulonglong2 c = cp[kk];
                const u64 nx = fma2(TWOS, bAx, fma2(bBx, NEG1, c.x));
                const u64 nz = fma2(TWOS, bAz, fma2(bBz, NEG1, c.y));
                bBx = bAx;  bBz = bAz;
                bAx = nx;   bAz = nz;
            }
            const float4 c0 = coef[0];
            const float2 aX = unpack2(bAx), aZ = unpack2(bAz);
            const float2 bX = unpack2(bBx), bZ = unpack2(bBz);
            const float p0 = fmaf(s, aX.x, c0.x - bX.x);
            const float p1 = fmaf(s, aX.y, c0.y - bX.y);
            const float q0 = fmaf(s, aZ.x, c0.z - bZ.x);
            const float q1 = fmaf(s, aZ.y, c0.w - bZ.y);

            // square + JVP of square
            const float a  = p0 * p0;
            const float b  = p1 * p1;
            const float da = 2.0f * p0 * q0;
            const float db = 2.0f * p1 * q1;

            // trig epilogue (cos(x)-1 = -2*sin^2(x/2), cancellation-free)
            const float s2v = __sinf(0.5f * x);
            const float cm1 = -2.0f * s2v * s2v;
            const float sa  = __sinf(x);
            const float ca  = 1.0f + cm1;

            xp  = a * cm1;
            yp  = b * sa;
            xpp = fmaf(da, cm1, -a * sa);
            ypp = fmaf(db, sa,  b * ca);

            out[           row + t] = xp;
            out[AR       + row + t] = yp;
            out[2 * AR   + row + t] = xpp;
            out[3 * AR   + row + t] = ypp;

            if (t == HALF - 1) xlast_s = xp;   // only (k=0, tid=0)
        }

        if (k == 0) {            // uniform branch: all threads participate
            __syncthreads();
            xlast = xlast_s;
        }

        // mirror writes: dest col 2048 - t for t in 0..1023
        if (active && t < HALF - 1) {
            const int c2 = (NCOL - 1) - t;
            out[           row + c2] = 2.0f * xlast - xp;
            out[AR       + row + c2] = yp;
            out[2 * AR   + row + c2] = xpp;
            out[3 * AR   + row + c2] = -ypp;
        }
    }
}

extern "C" void kernel_launch(void* const* d_in, const int* in_sizes, int n_in,
                              void* d_out, int out_size)
{
    const float* alpha = (const float*)d_in[0];
    const float* w0    = (const float*)d_in[1];
    const float* w1    = (const float*)d_in[2];
    const float* w2    = (const float*)d_in[3];
    const float* b0    = (const float*)d_in[4];
    const float* b1    = (const float*)d_in[5];
    const float* b2    = (const float*)d_in[6];
    float* out = (float*)d_out;

    sofanet_coef_kernel<<<NAB * 2, TPBA>>>(w0, w1, w2, b0, b1, b2);
    sofanet_eval_kernel<<<NAB, TPB2>>>(alpha, out);
}

// round 16
// speedup vs baseline: 1.1501x; 1.0936x over previous
#include <cuda_runtime.h>

// SofaNetEllipse via Chebyshev spectral compression (NQ=16) — two kernels.
//
// Kernel A: R12's verified monolithic coef kernel (best measured A): exact
//           MLP+JVP at 16 Chebyshev nodes, 2 threads/node, TPBA=32, scalar
//           fp32 layer-1, DCT -> 16 float4 coeffs per network.
// Kernel B: Clenshaw eval, TPB=128, grid 2048 = (network, column-half) —
//           near-single-wave residency (kills R12-B's straggler tail),
//           direct t=m mapping, analytic xlast (no syncs in the loop).

#define NAB   1024
#define NCOL  2049
#define HALF  1025
#define H     64
#define TPBA  32      // kernel A: one warp, 2 threads/node x 16 nodes
#define TPBB  128     // kernel B
#define NQ    16      // Chebyshev nodes / coefficients

#define XH    0.7853981633974483f   // pi/4  (half-width of [0, pi/2])
#define INVXH 1.2732395447351628f   // 4/pi  (s = alpha*INVXH - 1)

typedef unsigned long long u64;

__device__ __align__(16) float4 g_coef[NAB * NQ];   // 256 KB scratch

__device__ __forceinline__ float fast_tanh(float x) {
    // tanh(x) = 1 - 2/(exp(2x)+1); abs err ~1e-6, saturates correctly.
    float e = __expf(x + x);
    return 1.0f - __fdividef(2.0f, e + 1.0f);
}

__device__ __forceinline__ u64 fma2(u64 a, u64 b, u64 c) {
    u64 d;
    asm("fma.rn.f32x2 %0, %1, %2, %3;" : "=l"(d) : "l"(a), "l"(b), "l"(c));
    return d;
}
__device__ __forceinline__ u64 pack2(float lo, float hi) {
    u64 r;
    asm("mov.b64 %0, {%1, %2};" : "=l"(r) : "f"(lo), "f"(hi));
    return r;
}
__device__ __forceinline__ float2 unpack2(u64 v) {
    float2 r;
    asm("mov.b64 {%0, %1}, %2;" : "=f"(r.x), "=f"(r.y) : "l"(v));
    return r;
}

// ======================= Kernel A: coefficients =======================
__global__ __launch_bounds__(TPBA)
void sofanet_coef_kernel(const float* __restrict__ w0,
                         const float* __restrict__ w1,
                         const float* __restrict__ w2,
                         const float* __restrict__ b0,
                         const float* __restrict__ b1,
                         const float* __restrict__ b2)
{
    const int n   = blockIdx.x;   // network id
    const int tid = threadIdx.x;  // 0..31

    __shared__ __align__(16) float  w1s[H * H];   // 16 KB
    __shared__ float w0s[H], b0s[H], b1s[H];
    __shared__ float w2s[2 * H];
    __shared__ float b2s[2];
    __shared__ __align__(16) float4 nodes[NQ];    // f(x_q) = (p0,p1,q0,q1)

    // ---- stage weights (32 threads) ----
    {
        const float4* src = reinterpret_cast<const float4*>(w1 + (size_t)n * H * H);
        float4* dst = reinterpret_cast<float4*>(w1s);
        #pragma unroll
        for (int i = tid; i < (H * H) / 4; i += TPBA) dst[i] = src[i];

        w0s[tid]      = w0[(size_t)n * H + tid];
        w0s[tid + 32] = w0[(size_t)n * H + tid + 32];
        b0s[tid]      = b0[(size_t)n * H + tid];
        b0s[tid + 32] = b0[(size_t)n * H + tid + 32];
        b1s[tid]      = b1[(size_t)n * H + tid];
        b1s[tid + 32] = b1[(size_t)n * H + tid + 32];
        #pragma unroll
        for (int r = 0; r < 4; ++r)
            w2s[tid + 32 * r] = w2[(size_t)n * 2 * H + tid + 32 * r];
        if (tid < 2) b2s[tid] = b2[(size_t)n * 2 + tid];
    }
    __syncthreads();

    // ---- exact MLP + JVP at 16 Chebyshev nodes (2 threads per node) ----
    {
        const int q    = tid >> 1;        // node 0..15
        const int half = tid & 1;         // row half
        const float theta = (2 * q + 1) * (3.14159265358979323846f / (2.0f * NQ));
        const float xq = XH * (1.0f + cosf(theta));   // node in [0, pi/2]

        float h1[H], d1[H];
        #pragma unroll
        for (int j = 0; j < H; ++j) {
            const float w  = w0s[j];
            const float th = fast_tanh(fmaf(w, xq, b0s[j]));
            h1[j] = th;
            d1[j] = (1.0f - th * th) * w;
        }

        float p0 = 0.f, p1 = 0.f, q0 = 0.f, q1 = 0.f;
        const int i0 = half * 32;
        #pragma unroll 2
        for (int i = i0; i < i0 + 32; ++i) {
            float u = b1s[i], v = 0.f;
            const float* ra = &w1s[i * H];
            #pragma unroll
            for (int j = 0; j < H; j += 4) {
                const float4 wa = *reinterpret_cast<const float4*>(ra + j);
                u = fmaf(wa.x, h1[j    ], u);
                u = fmaf(wa.y, h1[j + 1], u);
                u = fmaf(wa.z, h1[j + 2], u);
                u = fmaf(wa.w, h1[j + 3], u);
                v = fmaf(wa.x, d1[j    ], v);
                v = fmaf(wa.y, d1[j + 1], v);
                v = fmaf(wa.z, d1[j + 2], v);
                v = fmaf(wa.w, d1[j + 3], v);
            }
            const float th = fast_tanh(u);
            const float dd = (1.0f - th * th) * v;
            p0 = fmaf(w2s[i    ], th, p0);
            p1 = fmaf(w2s[H + i], th, p1);
            q0 = fmaf(w2s[i    ], dd, q0);
            q1 = fmaf(w2s[H + i], dd, q1);
        }

        // combine the two halves (adjacent lanes, same warp, all lanes active)
        p0 += __shfl_xor_sync(0xFFFFFFFFu, p0, 1);
        p1 += __shfl_xor_sync(0xFFFFFFFFu, p1, 1);
        q0 += __shfl_xor_sync(0xFFFFFFFFu, q0, 1);
        q1 += __shfl_xor_sync(0xFFFFFFFFu, q1, 1);

        if (half == 0)
            nodes[q] = make_float4(p0 + b2s[0], p1 + b2s[1], q0, q1);
    }
    __syncthreads();

    // ---- DCT -> Chebyshev coefficients (threads 0..15) -> global ----
    if (tid < NQ) {
        const int k = tid;
        float s0 = 0.f, s1 = 0.f, s2 = 0.f, s3 = 0.f;
        #pragma unroll
        for (int q = 0; q < NQ; ++q) {
            const int m = (k * (2 * q + 1)) & (4 * NQ - 1);   // angle mod 2*pi
            const float c = __cosf((float)m * (3.14159265358979323846f / (2.0f * NQ)));
            const float4 f = nodes[q];
            s0 = fmaf(c, f.x, s0);
            s1 = fmaf(c, f.y, s1);
            s2 = fmaf(c, f.z, s2);
            s3 = fmaf(c, f.w, s3);
        }
        const float sc = (k == 0) ? (1.0f / NQ) : (2.0f / NQ);
        g_coef[n * NQ + k] = make_float4(s0 * sc, s1 * sc, s2 * sc, s3 * sc);
    }
}

// ======================= Kernel B: evaluation =========================
// grid = 2048: block = (network n = blk>>1, column-half hf = blk&1).
// half 0: t = 0..511;  half 1: t = 512..1024 (513 columns).
__global__ __launch_bounds__(TPBB)
void sofanet_eval_kernel(const float* __restrict__ alpha,
                         float* __restrict__ out)
{
    const int blk = blockIdx.x;
    const int n   = blk >> 1;     // network id
    const int hf  = blk & 1;      // column half
    const int tid = threadIdx.x;

    __shared__ __align__(16) float4 coef[NQ];   // 256 B

    // stage coefficients (64 floats, coalesced; TPBB=128 >= 64)
    if (tid < NQ * 4) {
        const float* src = (const float*)(g_coef + (size_t)n * NQ);
        ((float*)coef)[tid] = src[tid];
    }
    __syncthreads();

    const size_t AR  = (size_t)NAB * NCOL;
    const size_t row = (size_t)n * NCOL;

    // xlast = xp at alpha=pi/2 (t=1024): s=1, T_k(1)=1 => p0 = sum_k c_k.x,
    // cos-1 = -1 => xlast = -(sum c_k.x)^2. (R13-verified numerically.)
    float xlast;
    {
        float S = 0.f;
        #pragma unroll
        for (int k = 0; k < NQ; ++k) S += coef[k].x;
        xlast = -(S * S);
    }

    const u64 NEG1 = pack2(-1.0f, -1.0f);
    const int base  = hf * 512;
    const int limit = 512 + hf;          // 512 cols (half 0) / 513 (half 1)
    const int ntile = hf ? 5 : 4;

    for (int k = 0; k < ntile; ++k) {
        const int ml = k * TPBB + tid;   // local index within this half
        if (ml >= limit) continue;
        const int t = base + ml;         // direct mapping, no remap

        const float x = alpha[t];
        const float s = fmaf(x, INVXH, -1.0f);
        const float twos = s + s;
        const u64 TWOS = pack2(twos, twos);

        // Clenshaw (packed): b_k = c_k - b_{k+2} + 2s*b_{k+1}
        u64 bAx = 0ull, bAz = 0ull;   // b_{k+1}: (x,y) and (z,w) lanes
        u64 bBx = 0ull, bBz = 0ull;   // b_{k+2}
        const ulonglong2* cp = reinterpret_cast<const ulonglong2*>(coef);
        #pragma unroll
        for (int kk = NQ - 1; kk >= 1; --kk) {
            const ulonglong2 c = cp[kk];
            const u64 nx = fma2(TWOS, bAx, fma2(bBx, NEG1, c.x));
            const u64 nz = fma2(TWOS, bAz, fma2(bBz, NEG1, c.y));
            bBx = bAx;  bBz = bAz;
            bAx = nx;   bAz = nz;
        }
        const float4 c0 = coef[0];
        const float2 aX = unpack2(bAx), aZ = unpack2(bAz);
        const float2 bX = unpack2(bBx), bZ = unpack2(bBz);
        const float p0 = fmaf(s, aX.x, c0.x - bX.x);
        const float p1 = fmaf(s, aX.y, c0.y - bX.y);
        const float q0 = fmaf(s, aZ.x, c0.z - bZ.x);
        const float q1 = fmaf(s, aZ.y, c0.w - bZ.y);

        // square + JVP of square
        const float a  = p0 * p0;
        const float b  = p1 * p1;
        const float da = 2.0f * p0 * q0;
        const float db = 2.0f * p1 * q1;

        // trig epilogue (cos(x)-1 = -2*sin^2(x/2), cancellation-free)
        const float s2v = __sinf(0.5f * x);
        const float cm1 = -2.0f * s2v * s2v;
        const float sa  = __sinf(x);
        const float ca  = 1.0f + cm1;

        const float xp  = a * cm1;
        const float yp  = b * sa;
        const float xpp = fmaf(da, cm1, -a * sa);
        const float ypp = fmaf(db, sa,  b * ca);

        // primary writes (t = 0..1024)
        out[           row + t] = xp;
        out[AR       + row + t] = yp;
        out[2 * AR   + row + t] = xpp;
        out[3 * AR   + row + t] = ypp;

        // mirror writes: dest col 2048 - t for t in 0..1023
        if (t < HALF - 1) {
            const int c2 = (NCOL - 1) - t;
            out[           row + c2] = 2.0f * xlast - xp;
            out[AR       + row + c2] = yp;
            out[2 * AR   + row + c2] = xpp;
            out[3 * AR   + row + c2] = -ypp;
        }
    }
}

extern "C" void kernel_launch(void* const* d_in, const int* in_sizes, int n_in,
                              void* d_out, int out_size)
{
    const float* alpha = (const float*)d_in[0];
    const float* w0    = (const float*)d_in[1];
    const float* w1    = (const float*)d_in[2];
    const float* w2    = (const float*)d_in[3];
    const float* b0    = (const float*)d_in[4];
    const float* b1    = (const float*)d_in[5];
    const float* b2    = (const float*)d_in[6];
    float* out = (float*)d_out;

    sofanet_coef_kernel<<<NAB, TPBA>>>(w0, w1, w2, b0, b1, b2);
    sofanet_eval_kernel<<<NAB * 2, TPBB>>>(alpha, out);
}